// round 2
// baseline (speedup 1.0000x reference)
#include <cuda_runtime.h>

// 2-layer KAN (1 -> 8 -> 1), B = 524288, uniform cubic B-spline grid:
// knots g[j] = (j-3)*0.4 - 1.0, j = 0..11. Bases nonzero only on [-2.2, 2.2).
// For x in interval j (g[j] <= x < g[j+1]), t = (x - g[j])/h, the only nonzero
// final bases are indices j-3..j (clipped to [0,7]) with the cardinal cubics.

__device__ __forceinline__ float silu_f(float x) {
    // x * sigmoid(x); MUFU-based exp + fast divide. Accurate to ~1e-6 rel.
    return x * __fdividef(1.0f, 1.0f + __expf(-x));
}

__device__ __forceinline__ void spline_basis(float s, float jf,
                                             float& b0, float& b1,
                                             float& b2, float& b3) {
    const float c6 = 1.0f / 6.0f;
    float tt = s - jf;
    float u  = 1.0f - tt;
    float t2 = tt * tt;
    float t3 = t2 * tt;
    b0 = u * u * u * c6;
    b1 = (3.0f * t3 - 6.0f * t2 + 4.0f) * c6;
    b2 = (-3.0f * t3 + 3.0f * t2 + 3.0f * tt + 1.0f) * c6;
    b3 = t3 * c6;
}

__global__ __launch_bounds__(256)
void kan2_kernel(const float4* __restrict__ xv, float4* __restrict__ outv,
                 const float* __restrict__ bw1, const float* __restrict__ sw1,
                 const float* __restrict__ sc1, const float* __restrict__ bw2,
                 const float* __restrict__ sw2, const float* __restrict__ sc2,
                 int n4)
{
    // Weights staged in shared. Layer-1 spline table transposed [k][o] so one
    // basis value broadcasts across all 8 hidden units via two float4 LDS.
    __shared__ __align__(16) float s_w1t[8][8];  // [k][o] = sw1[o][k]*sc1[o]
    __shared__ __align__(16) float s_w2[8][8];   // [i][k] = sw2[i][k]*sc2[i]
    __shared__ float s_bw1[8], s_bw2[8];

    int t = threadIdx.x;
    if (t < 64) {
        int o = t >> 3, k = t & 7;
        s_w1t[k][o] = sw1[o * 8 + k] * sc1[o];
        s_w2[o][k]  = sw2[o * 8 + k] * sc2[o];
    }
    if (t < 8) { s_bw1[t] = bw1[t]; s_bw2[t] = bw2[t]; }
    __syncthreads();

    int idx = blockIdx.x * blockDim.x + threadIdx.x;
    if (idx >= n4) return;

    float4 xin = xv[idx];
    float xs[4] = {xin.x, xin.y, xin.z, xin.w};
    float r[4];

    #pragma unroll
    for (int e = 0; e < 4; e++) {
        float x = xs[e];

        // ---------------- Layer 1: h[o] = silu(x)*bw1[o] + spline ----------
        float h[8];
        float si = silu_f(x);
        #pragma unroll
        for (int o = 0; o < 8; o++) h[o] = si * s_bw1[o];

        float s = (x + 2.2f) * 2.5f;       // (x - g[0]) / h
        float jf = floorf(s);
        int j = (int)jf;
        if (j >= 0 && j <= 10) {
            float b0, b1, b2, b3;
            spline_basis(s, jf, b0, b1, b2, b3);
            int i0 = j - 3;
            float bv[4] = {b0, b1, b2, b3};
            #pragma unroll
            for (int m = 0; m < 4; m++) {
                int ri = i0 + m;
                if (ri >= 0 && ri < 8) {
                    float b = bv[m];
                    float4 lo = *(const float4*)&s_w1t[ri][0];
                    float4 hi = *(const float4*)&s_w1t[ri][4];
                    h[0] += b * lo.x; h[1] += b * lo.y;
                    h[2] += b * lo.z; h[3] += b * lo.w;
                    h[4] += b * hi.x; h[5] += b * hi.y;
                    h[6] += b * hi.z; h[7] += b * hi.w;
                }
            }
        }

        // ---------------- Layer 2: out = sum_i silu(h[i])*bw2[i] + spline --
        float acc = 0.0f;
        #pragma unroll
        for (int i = 0; i < 8; i++) {
            float hv = h[i];
            acc += silu_f(hv) * s_bw2[i];

            float s2  = (hv + 2.2f) * 2.5f;
            float jf2 = floorf(s2);
            int j2 = (int)jf2;
            if (j2 >= 0 && j2 <= 10) {
                float b0, b1, b2, b3;
                spline_basis(s2, jf2, b0, b1, b2, b3);
                int i0 = j2 - 3;
                const float* wr = s_w2[i];
                if (i0     >= 0 && i0     < 8) acc += b0 * wr[i0];
                if (i0 + 1 >= 0 && i0 + 1 < 8) acc += b1 * wr[i0 + 1];
                if (i0 + 2 >= 0 && i0 + 2 < 8) acc += b2 * wr[i0 + 2];
                if (i0 + 3 >= 0 && i0 + 3 < 8) acc += b3 * wr[i0 + 3];
            }
        }
        r[e] = acc;
    }

    outv[idx] = make_float4(r[0], r[1], r[2], r[3]);
}

extern "C" void kernel_launch(void* const* d_in, const int* in_sizes, int n_in,
                              void* d_out, int out_size) {
    const float* x   = (const float*)d_in[0];
    const float* bw1 = (const float*)d_in[1];
    const float* sw1 = (const float*)d_in[2];
    const float* sc1 = (const float*)d_in[3];
    const float* bw2 = (const float*)d_in[4];
    const float* sw2 = (const float*)d_in[5];
    const float* sc2 = (const float*)d_in[6];

    int n  = in_sizes[0];     // 524288, divisible by 4
    int n4 = n / 4;
    int threads = 256;
    int blocks  = (n4 + threads - 1) / threads;

    kan2_kernel<<<blocks, threads>>>((const float4*)x, (float4*)d_out,
                                     bw1, sw1, sc1, bw2, sw2, sc2, n4);
}

// round 3
// speedup vs baseline: 1.2167x; 1.2167x over previous
#include <cuda_runtime.h>

// ---------------------------------------------------------------------------
// 2-layer KAN (1 -> 8 -> 1) over B scalars == a scalar function out = f(x).
// Strategy: per launch, rebuild a piecewise-cubic coefficient LUT of f on
// [-8, 8) with N=4096 intervals (h = 1/256, exact in fp32), then evaluate
// each element with one float4 gather + 3 FMAs. Exact path as fallback for
// |x| outside the table (never hit for N(0,1) inputs, kept for correctness).
// ---------------------------------------------------------------------------

#define LUT_N 4096
#define LUT_INVH 256.0f         // 1/h, exact
#define LUT_H   (1.0f / 256.0f) // h,   exact
#define LUT_OFS 2048.0f         // -X0/h = 8*256, exact

__device__ __align__(16) float4 g_coef[LUT_N];

__device__ __forceinline__ float silu_f(float x) {
    return x * __fdividef(1.0f, 1.0f + __expf(-x));
}

__device__ __forceinline__ void spline_basis(float s, float jf, float* b) {
    const float c6 = 1.0f / 6.0f;
    float t = s - jf;
    float u = 1.0f - t;
    float t2 = t * t, t3 = t2 * t;
    b[0] = u * u * u * c6;
    b[1] = (3.0f * t3 - 6.0f * t2 + 4.0f) * c6;
    b[2] = (-3.0f * t3 + 3.0f * t2 + 3.0f * t + 1.0f) * c6;
    b[3] = t3 * c6;
}

// Exact 2-layer KAN evaluation (matches reference; uniform-grid closed form).
__device__ float kan_exact(float x,
    const float* __restrict__ bw1, const float* __restrict__ sw1,
    const float* __restrict__ sc1, const float* __restrict__ bw2,
    const float* __restrict__ sw2, const float* __restrict__ sc2)
{
    float h[8];
    float si = silu_f(x);
    #pragma unroll
    for (int o = 0; o < 8; o++) h[o] = si * __ldg(bw1 + o);

    float s = (x + 2.2f) * 2.5f;
    float jf = floorf(s);
    int j = (int)jf;
    if (j >= 0 && j <= 10) {
        float b[4];
        spline_basis(s, jf, b);
        #pragma unroll
        for (int m = 0; m < 4; m++) {
            int ri = j - 3 + m;
            if (ri >= 0 && ri < 8) {
                float bm = b[m];
                #pragma unroll
                for (int o = 0; o < 8; o++)
                    h[o] += bm * __ldg(sw1 + o * 8 + ri) * __ldg(sc1 + o);
            }
        }
    }

    float acc = 0.0f;
    #pragma unroll
    for (int i = 0; i < 8; i++) {
        float hv = h[i];
        acc += silu_f(hv) * __ldg(bw2 + i);
        float s2  = (hv + 2.2f) * 2.5f;
        float jf2 = floorf(s2);
        int j2 = (int)jf2;
        if (j2 >= 0 && j2 <= 10) {
            float b[4];
            spline_basis(s2, jf2, b);
            float sc = __ldg(sc2 + i);
            #pragma unroll
            for (int m = 0; m < 4; m++) {
                int ri = j2 - 3 + m;
                if (ri >= 0 && ri < 8)
                    acc += b[m] * __ldg(sw2 + i * 8 + ri) * sc;
            }
        }
    }
    return acc;
}

// Build LUT: one warp per 29 intervals. Lane l evaluates f at node
// m = base-1+l (x = -8 + m/256); interval k = base+l takes a Lagrange cubic
// through nodes k-1..k+2 (lanes l..l+3 via shfl). 4th-order interp away from
// knots; ~h^3 * |jump f'''| /40 ~ 1e-7 near knots.
__global__ void build_lut_kernel(
    const float* __restrict__ bw1, const float* __restrict__ sw1,
    const float* __restrict__ sc1, const float* __restrict__ bw2,
    const float* __restrict__ sw2, const float* __restrict__ sc2)
{
    int lane = threadIdx.x & 31;
    int base = blockIdx.x * 29;
    int m = base - 1 + lane;
    float xnode = fmaf((float)m, LUT_H, -8.0f);   // exact grid
    float y0 = kan_exact(xnode, bw1, sw1, sc1, bw2, sw2, sc2);

    float y1 = __shfl_down_sync(0xffffffffu, y0, 1);
    float y2 = __shfl_down_sync(0xffffffffu, y0, 2);
    float y3 = __shfl_down_sync(0xffffffffu, y0, 3);

    int k = base + lane;
    if (lane <= 28 && k < LUT_N) {
        // Lagrange cubic through (u=-1,y0),(0,y1),(1,y2),(2,y3):
        float c0 = y1;
        float c1 = -y0 * (1.0f / 3.0f) - 0.5f * y1 + y2 - y3 * (1.0f / 6.0f);
        float c2 =  0.5f * y0 - y1 + 0.5f * y2;
        float c3 = (y3 - y0) * (1.0f / 6.0f) + 0.5f * (y1 - y2);
        g_coef[k] = make_float4(c0, c1, c2, c3);
    }
}

__global__ __launch_bounds__(256)
void kan_lut_kernel(const float4* __restrict__ xv, float4* __restrict__ outv,
                    const float* __restrict__ bw1, const float* __restrict__ sw1,
                    const float* __restrict__ sc1, const float* __restrict__ bw2,
                    const float* __restrict__ sw2, const float* __restrict__ sc2,
                    int n4)
{
    int idx = blockIdx.x * blockDim.x + threadIdx.x;
    if (idx >= n4) return;

    float4 xin = xv[idx];
    float xs[4] = {xin.x, xin.y, xin.z, xin.w};
    float r[4];
    bool oor[4];
    bool oor_any = false;

    #pragma unroll
    for (int e = 0; e < 4; e++) {
        float x = xs[e];
        float s = fmaf(x, LUT_INVH, LUT_OFS);   // exact constants
        float kf = floorf(s);
        int k = (int)kf;
        oor[e] = (k < 0) | (k >= LUT_N);
        oor_any |= oor[e];
        k = max(0, min(LUT_N - 1, k));
        // Recompute u with exact integer offset for full precision:
        float u = fmaf(x, LUT_INVH, LUT_OFS - (float)k);
        float4 c = __ldg(&g_coef[k]);
        r[e] = fmaf(fmaf(fmaf(c.w, u, c.z), u, c.y), u, c.x);
    }

    if (oor_any) {   // essentially never taken for N(0,1) inputs
        #pragma unroll
        for (int e = 0; e < 4; e++)
            if (oor[e]) r[e] = kan_exact(xs[e], bw1, sw1, sc1, bw2, sw2, sc2);
    }

    outv[idx] = make_float4(r[0], r[1], r[2], r[3]);
}

extern "C" void kernel_launch(void* const* d_in, const int* in_sizes, int n_in,
                              void* d_out, int out_size) {
    const float* x   = (const float*)d_in[0];
    const float* bw1 = (const float*)d_in[1];
    const float* sw1 = (const float*)d_in[2];
    const float* sc1 = (const float*)d_in[3];
    const float* bw2 = (const float*)d_in[4];
    const float* sw2 = (const float*)d_in[5];
    const float* sc2 = (const float*)d_in[6];

    int n  = in_sizes[0];   // 524288
    int n4 = n / 4;

    // 4096 intervals / 29 per warp -> 142 single-warp blocks.
    build_lut_kernel<<<142, 32>>>(bw1, sw1, sc1, bw2, sw2, sc2);

    int threads = 256;
    int blocks  = (n4 + threads - 1) / threads;
    kan_lut_kernel<<<blocks, threads>>>((const float4*)x, (float4*)d_out,
                                        bw1, sw1, sc1, bw2, sw2, sc2, n4);
}

// round 4
// speedup vs baseline: 1.6525x; 1.3582x over previous
#include <cuda_runtime.h>

// ---------------------------------------------------------------------------
// 2-layer KAN (1 -> 8 -> 1) == scalar function out = f(x). Per launch:
// (1) build piecewise-cubic LUT of f on [-8,8), N=4096 (h=1/256, exact fp32),
//     one thread per (node, unit) since f is separable over the 8 hidden units;
// (2) evaluate: k=floor((x+8)*256), float4 coef gather, Horner. 16 elems/thread
//     for memory-level parallelism. Exact-path fallback for |x|>=8 (never hit
//     for N(0,1) inputs; kept for correctness).
// ---------------------------------------------------------------------------

#define LUT_N 4096
#define LUT_INVH 256.0f
#define LUT_H   (1.0f / 256.0f)
#define LUT_OFS 2048.0f
#define BATCH 4                      // float4s per thread in main kernel

__device__ __align__(16) float4 g_coef[LUT_N];

__device__ __forceinline__ float silu_f(float x) {
    return x * __fdividef(1.0f, 1.0f + __expf(-x));
}

__device__ __forceinline__ void spline_basis(float s, float jf, float* b) {
    const float c6 = 1.0f / 6.0f;
    float t = s - jf;
    float u = 1.0f - t;
    float t2 = t * t, t3 = t2 * t;
    b[0] = u * u * u * c6;
    b[1] = (3.0f * t3 - 6.0f * t2 + 4.0f) * c6;
    b[2] = (-3.0f * t3 + 3.0f * t2 + 3.0f * t + 1.0f) * c6;
    b[3] = t3 * c6;
}

// Per-unit contribution to f(x): layer1 unit u -> h, then layer2 unit u on h.
__device__ __forceinline__ float kan_unit(float x, int u,
    const float* __restrict__ bw1, const float* __restrict__ sw1,
    const float* __restrict__ sc1, const float* __restrict__ bw2,
    const float* __restrict__ sw2, const float* __restrict__ sc2)
{
    float h = silu_f(x) * __ldg(bw1 + u);
    float s = (x + 2.2f) * 2.5f;
    float jf = floorf(s);
    int j = (int)jf;
    if (j >= 0 && j <= 10) {
        float b[4];
        spline_basis(s, jf, b);
        float sc = __ldg(sc1 + u);
        #pragma unroll
        for (int m = 0; m < 4; m++) {
            int ri = j - 3 + m;
            if (ri >= 0 && ri < 8) h += b[m] * __ldg(sw1 + u * 8 + ri) * sc;
        }
    }
    float c = silu_f(h) * __ldg(bw2 + u);
    float s2 = (h + 2.2f) * 2.5f;
    float jf2 = floorf(s2);
    int j2 = (int)jf2;
    if (j2 >= 0 && j2 <= 10) {
        float b[4];
        spline_basis(s2, jf2, b);
        float sc = __ldg(sc2 + u);
        #pragma unroll
        for (int m = 0; m < 4; m++) {
            int ri = j2 - 3 + m;
            if (ri >= 0 && ri < 8) c += b[m] * __ldg(sw2 + u * 8 + ri) * sc;
        }
    }
    return c;
}

// Full exact eval (fallback for out-of-table x in main kernel).
__device__ float kan_exact(float x,
    const float* __restrict__ bw1, const float* __restrict__ sw1,
    const float* __restrict__ sc1, const float* __restrict__ bw2,
    const float* __restrict__ sw2, const float* __restrict__ sc2)
{
    float acc = 0.0f;
    #pragma unroll
    for (int u = 0; u < 8; u++)
        acc += kan_unit(x, u, bw1, sw1, sc1, bw2, sw2, sc2);
    return acc;
}

// Build: block = 256 threads = 32 nodes x 8 units; covers 29 intervals.
// tid&7 = unit, tid>>3 = local node. Reduce units via shfl_xor, then
// threads 0..28 form the Lagrange cubic per interval from shared node values.
__global__ __launch_bounds__(256)
void build_lut_kernel(
    const float* __restrict__ bw1, const float* __restrict__ sw1,
    const float* __restrict__ sc1, const float* __restrict__ bw2,
    const float* __restrict__ sw2, const float* __restrict__ sc2)
{
    __shared__ float s_y[32];
    int tid  = threadIdx.x;
    int unit = tid & 7;
    int nl   = tid >> 3;                      // 0..31
    int m    = blockIdx.x * 29 - 1 + nl;
    float x  = fmaf((float)m, LUT_H, -8.0f);  // exact grid node

    float c = kan_unit(x, unit, bw1, sw1, sc1, bw2, sw2, sc2);
    c += __shfl_xor_sync(0xffffffffu, c, 1);
    c += __shfl_xor_sync(0xffffffffu, c, 2);
    c += __shfl_xor_sync(0xffffffffu, c, 4);
    if (unit == 0) s_y[nl] = c;
    __syncthreads();

    if (tid < 29) {
        int k = blockIdx.x * 29 + tid;
        if (k < LUT_N) {
            float y0 = s_y[tid], y1 = s_y[tid + 1];
            float y2 = s_y[tid + 2], y3 = s_y[tid + 3];
            // Lagrange cubic through (-1,y0),(0,y1),(1,y2),(2,y3) in u:
            float c0 = y1;
            float c1 = -y0 * (1.0f/3.0f) - 0.5f * y1 + y2 - y3 * (1.0f/6.0f);
            float c2 =  0.5f * y0 - y1 + 0.5f * y2;
            float c3 = (y3 - y0) * (1.0f/6.0f) + 0.5f * (y1 - y2);
            g_coef[k] = make_float4(c0, c1, c2, c3);
        }
    }
}

__global__ __launch_bounds__(256)
void kan_lut_kernel(const float4* __restrict__ xv, float4* __restrict__ outv,
                    const float* __restrict__ bw1, const float* __restrict__ sw1,
                    const float* __restrict__ sc1, const float* __restrict__ bw2,
                    const float* __restrict__ sw2, const float* __restrict__ sc2,
                    int n4)
{
    int t      = blockIdx.x * blockDim.x + threadIdx.x;
    int stride = gridDim.x * blockDim.x;

    float4 xin[BATCH];
    bool valid[BATCH];
    #pragma unroll
    for (int jb = 0; jb < BATCH; jb++) {
        int idx = t + jb * stride;
        valid[jb] = idx < n4;
        xin[jb] = valid[jb] ? xv[idx] : make_float4(0.f, 0.f, 0.f, 0.f);
    }

    float4 res[BATCH];
    bool oor_any = false;
    unsigned oor_mask = 0;

    #pragma unroll
    for (int jb = 0; jb < BATCH; jb++) {
        float xs[4] = {xin[jb].x, xin[jb].y, xin[jb].z, xin[jb].w};
        float r[4];
        #pragma unroll
        for (int e = 0; e < 4; e++) {
            float x = xs[e];
            float s = fmaf(x, LUT_INVH, LUT_OFS);
            float kf = floorf(s);
            int k = (int)kf;
            bool oo = (k < 0) | (k >= LUT_N);
            oor_any |= oo;
            if (oo) oor_mask |= 1u << (jb * 4 + e);
            k = max(0, min(LUT_N - 1, k));
            float u = fmaf(x, LUT_INVH, LUT_OFS - (float)k);
            float4 cf = __ldg(&g_coef[k]);
            r[e] = fmaf(fmaf(fmaf(cf.w, u, cf.z), u, cf.y), u, cf.x);
        }
        res[jb] = make_float4(r[0], r[1], r[2], r[3]);
    }

    if (oor_any) {  // essentially never taken for N(0,1) inputs
        #pragma unroll
        for (int jb = 0; jb < BATCH; jb++) {
            float* rp = (float*)&res[jb];
            const float* xp = (const float*)&xin[jb];
            #pragma unroll
            for (int e = 0; e < 4; e++)
                if (oor_mask & (1u << (jb * 4 + e)))
                    rp[e] = kan_exact(xp[e], bw1, sw1, sc1, bw2, sw2, sc2);
        }
    }

    #pragma unroll
    for (int jb = 0; jb < BATCH; jb++) {
        int idx = t + jb * stride;
        if (valid[jb]) outv[idx] = res[jb];
    }
}

extern "C" void kernel_launch(void* const* d_in, const int* in_sizes, int n_in,
                              void* d_out, int out_size) {
    const float* x   = (const float*)d_in[0];
    const float* bw1 = (const float*)d_in[1];
    const float* sw1 = (const float*)d_in[2];
    const float* sc1 = (const float*)d_in[3];
    const float* bw2 = (const float*)d_in[4];
    const float* sw2 = (const float*)d_in[5];
    const float* sc2 = (const float*)d_in[6];

    int n  = in_sizes[0];   // 524288
    int n4 = n / 4;         // 131072

    build_lut_kernel<<<(LUT_N + 28) / 29, 256>>>(bw1, sw1, sc1, bw2, sw2, sc2);

    int threads = 256;
    int blocks  = (n4 + threads * BATCH - 1) / (threads * BATCH);  // 128
    kan_lut_kernel<<<blocks, threads>>>((const float4*)x, (float4*)d_out,
                                        bw1, sw1, sc1, bw2, sw2, sc2, n4);
}

// round 6
// speedup vs baseline: 1.6763x; 1.0144x over previous
#include <cuda_runtime.h>

// ---------------------------------------------------------------------------
// 2-layer KAN (1 -> 8 -> 1) == scalar function out = f(x).
// (1) build piecewise-cubic LUT of f on [-8,8), N=1024 intervals (h=1/64,
//     exact fp32), one thread per (node, unit) — f separable over 8 units;
// (2) main kernel stages the 16KB LUT into shared memory per block (x loads
//     issued first to overlap DRAM latency), then each element is one random
//     LDS.128 + Horner. Exact fallback for |x|>=8 (never hit for N(0,1)).
// ---------------------------------------------------------------------------

#define LUT_N   1024
#define LUT_INVH 64.0f          // 1/h, exact
#define LUT_H   (1.0f / 64.0f)  // h,   exact
#define LUT_OFS 512.0f          // 8*64, exact
#define BATCH   2               // float4s per thread in main kernel

__device__ __align__(16) float4 g_coef[LUT_N];

__device__ __forceinline__ float silu_f(float x) {
    return x * __fdividef(1.0f, 1.0f + __expf(-x));
}

__device__ __forceinline__ void spline_basis(float s, float jf, float* b) {
    const float c6 = 1.0f / 6.0f;
    float t = s - jf;
    float u = 1.0f - t;
    float t2 = t * t, t3 = t2 * t;
    b[0] = u * u * u * c6;
    b[1] = (3.0f * t3 - 6.0f * t2 + 4.0f) * c6;
    b[2] = (-3.0f * t3 + 3.0f * t2 + 3.0f * t + 1.0f) * c6;
    b[3] = t3 * c6;
}

// Per-unit contribution to f(x): layer1 unit u -> h, then layer2 unit u on h.
__device__ __forceinline__ float kan_unit(float x, int u,
    const float* __restrict__ bw1, const float* __restrict__ sw1,
    const float* __restrict__ sc1, const float* __restrict__ bw2,
    const float* __restrict__ sw2, const float* __restrict__ sc2)
{
    float h = silu_f(x) * __ldg(bw1 + u);
    float s = (x + 2.2f) * 2.5f;
    float jf = floorf(s);
    int j = (int)jf;
    if (j >= 0 && j <= 10) {
        float b[4];
        spline_basis(s, jf, b);
        float sc = __ldg(sc1 + u);
        #pragma unroll
        for (int m = 0; m < 4; m++) {
            int ri = j - 3 + m;
            if (ri >= 0 && ri < 8) h += b[m] * __ldg(sw1 + u * 8 + ri) * sc;
        }
    }
    float c = silu_f(h) * __ldg(bw2 + u);
    float s2 = (h + 2.2f) * 2.5f;
    float jf2 = floorf(s2);
    int j2 = (int)jf2;
    if (j2 >= 0 && j2 <= 10) {
        float b[4];
        spline_basis(s2, jf2, b);
        float sc = __ldg(sc2 + u);
        #pragma unroll
        for (int m = 0; m < 4; m++) {
            int ri = j2 - 3 + m;
            if (ri >= 0 && ri < 8) c += b[m] * __ldg(sw2 + u * 8 + ri) * sc;
        }
    }
    return c;
}

// Full exact eval (fallback for out-of-table x in main kernel).
__device__ float kan_exact(float x,
    const float* __restrict__ bw1, const float* __restrict__ sw1,
    const float* __restrict__ sc1, const float* __restrict__ bw2,
    const float* __restrict__ sw2, const float* __restrict__ sc2)
{
    float acc = 0.0f;
    #pragma unroll
    for (int u = 0; u < 8; u++)
        acc += kan_unit(x, u, bw1, sw1, sc1, bw2, sw2, sc2);
    return acc;
}

// Build: block = 256 threads = 32 nodes x 8 units; covers 29 intervals.
__global__ __launch_bounds__(256)
void build_lut_kernel(
    const float* __restrict__ bw1, const float* __restrict__ sw1,
    const float* __restrict__ sc1, const float* __restrict__ bw2,
    const float* __restrict__ sw2, const float* __restrict__ sc2)
{
    __shared__ float s_y[32];
    int tid  = threadIdx.x;
    int unit = tid & 7;
    int nl   = tid >> 3;                      // 0..31
    int m    = blockIdx.x * 29 - 1 + nl;
    float x  = fmaf((float)m, LUT_H, -8.0f);  // exact grid node

    float c = kan_unit(x, unit, bw1, sw1, sc1, bw2, sw2, sc2);
    c += __shfl_xor_sync(0xffffffffu, c, 1);
    c += __shfl_xor_sync(0xffffffffu, c, 2);
    c += __shfl_xor_sync(0xffffffffu, c, 4);
    if (unit == 0) s_y[nl] = c;
    __syncthreads();

    if (tid < 29) {
        int k = blockIdx.x * 29 + tid;
        if (k < LUT_N) {
            float y0 = s_y[tid], y1 = s_y[tid + 1];
            float y2 = s_y[tid + 2], y3 = s_y[tid + 3];
            // Lagrange cubic through (-1,y0),(0,y1),(1,y2),(2,y3) in u:
            float c0 = y1;
            float c1 = -y0 * (1.0f/3.0f) - 0.5f * y1 + y2 - y3 * (1.0f/6.0f);
            float c2 =  0.5f * y0 - y1 + 0.5f * y2;
            float c3 = (y3 - y0) * (1.0f/6.0f) + 0.5f * (y1 - y2);
            g_coef[k] = make_float4(c0, c1, c2, c3);
        }
    }
}

__global__ __launch_bounds__(256)
void kan_lut_kernel(const float4* __restrict__ xv, float4* __restrict__ outv,
                    const float* __restrict__ bw1, const float* __restrict__ sw1,
                    const float* __restrict__ sc1, const float* __restrict__ bw2,
                    const float* __restrict__ sw2, const float* __restrict__ sc2,
                    int n4)
{
    __shared__ __align__(16) float4 s_lut[LUT_N];

    int tid  = threadIdx.x;
    int base = blockIdx.x * (256 * BATCH) + tid;

    // 1) Issue the x loads first (DRAM latency overlaps LUT staging).
    float4 xin[BATCH];
    bool valid[BATCH];
    #pragma unroll
    for (int jb = 0; jb < BATCH; jb++) {
        int idx = base + jb * 256;
        valid[jb] = idx < n4;
        xin[jb] = valid[jb] ? xv[idx] : make_float4(0.f, 0.f, 0.f, 0.f);
    }

    // 2) Stage LUT: 1024 float4 / 256 threads = 4 per thread, coalesced.
    #pragma unroll
    for (int jb = 0; jb < LUT_N / 256; jb++)
        s_lut[tid + jb * 256] = __ldg(&g_coef[tid + jb * 256]);
    __syncthreads();

    // 3) Evaluate: one random LDS.128 + Horner per element.
    float4 res[BATCH];
    bool oor_any = false;
    unsigned oor_mask = 0;

    #pragma unroll
    for (int jb = 0; jb < BATCH; jb++) {
        float xs[4] = {xin[jb].x, xin[jb].y, xin[jb].z, xin[jb].w};
        float r[4];
        #pragma unroll
        for (int e = 0; e < 4; e++) {
            float x = xs[e];
            float s = fmaf(x, LUT_INVH, LUT_OFS);
            float kf = floorf(s);
            int k = (int)kf;
            bool oo = (k < 0) | (k >= LUT_N);
            oor_any |= oo;
            if (oo) oor_mask |= 1u << (jb * 4 + e);
            k = max(0, min(LUT_N - 1, k));
            float u = fmaf(x, LUT_INVH, LUT_OFS - (float)k);
            float4 cf = s_lut[k];
            r[e] = fmaf(fmaf(fmaf(cf.w, u, cf.z), u, cf.y), u, cf.x);
        }
        res[jb] = make_float4(r[0], r[1], r[2], r[3]);
    }

    if (oor_any) {  // essentially never taken for N(0,1) inputs
        #pragma unroll
        for (int jb = 0; jb < BATCH; jb++) {
            float* rp = (float*)&res[jb];
            const float* xp = (const float*)&xin[jb];
            #pragma unroll
            for (int e = 0; e < 4; e++)
                if (oor_mask & (1u << (jb * 4 + e)))
                    rp[e] = kan_exact(xp[e], bw1, sw1, sc1, bw2, sw2, sc2);
        }
    }

    #pragma unroll
    for (int jb = 0; jb < BATCH; jb++) {
        int idx = base + jb * 256;
        if (valid[jb]) outv[idx] = res[jb];
    }
}

extern "C" void kernel_launch(void* const* d_in, const int* in_sizes, int n_in,
                              void* d_out, int out_size) {
    const float* x   = (const float*)d_in[0];
    const float* bw1 = (const float*)d_in[1];
    const float* sw1 = (const float*)d_in[2];
    const float* sc1 = (const float*)d_in[3];
    const float* bw2 = (const float*)d_in[4];
    const float* sw2 = (const float*)d_in[5];
    const float* sc2 = (const float*)d_in[6];

    int n  = in_sizes[0];   // 524288
    int n4 = n / 4;         // 131072

    build_lut_kernel<<<(LUT_N + 28) / 29, 256>>>(bw1, sw1, sc1, bw2, sw2, sc2);

    int per_block = 256 * BATCH;
    int blocks = (n4 + per_block - 1) / per_block;   // 256
    kan_lut_kernel<<<blocks, 256>>>((const float4*)x, (float4*)d_out,
                                    bw1, sw1, sc1, bw2, sw2, sc2, n4);
}